// round 8
// baseline (speedup 1.0000x reference)
#include <cuda_runtime.h>
#include <cuda_bf16.h>

// FixedRadiusNearNeighbors: B=4, N=65536, S=4096, G=40, P=16, K=32.
// One warp per (b,s) query. Lanes 0..26 own the 27 neighbour voxels.
//
// R6 changes vs R5:
//  - neighbour_voxel_list (83 MB) never read: content is coords+offset by
//    construction (broadcast meshgrid, data-independent) -> computed in regs.
//  - mask never read: mask == (voxel_counts > 0) by construction.
//  - output written exactly once per slot: slot k gets a candidate iff
//    k < total valid candidates (K == 32 == warpsize), else the centroid.
//    Removes the fill/overwrite double store and the __syncwarp.

#define Gv 40
#define Pv 16
#define Kv 32
#define Bv 4
#define Nv 65536
#define Sv 4096

__global__ __launch_bounds__(256)
void frnn_kernel(const float* __restrict__ pos,
                 const int*   __restrict__ centroids,
                 const int*   __restrict__ voxel_points,
                 const int*   __restrict__ voxel_counts,
                 float*       __restrict__ out)
{
    const unsigned FULL = 0xffffffffu;
    const int lane   = threadIdx.x & 31;
    const int warpId = threadIdx.x >> 5;
    const int q = blockIdx.x * (blockDim.x >> 5) + warpId;
    if (q >= Bv * Sv) return;
    const int b = q >> 12;            // q / Sv

    // --- centroid + its position (lane 0 loads, broadcast) ---
    int   c  = 0;
    float px = 0.f, py = 0.f, pz = 0.f;
    if (lane == 0) {
        c = __ldg(&centroids[q]);
        const float* pp = pos + (((size_t)b << 16) + c) * 3;
        px = __ldg(&pp[0]);
        py = __ldg(&pp[1]);
        pz = __ldg(&pp[2]);
    }
    c  = __shfl_sync(FULL, c, 0);
    px = __shfl_sync(FULL, px, 0);
    py = __shfl_sync(FULL, py, 0);
    pz = __shfl_sync(FULL, pz, 0);

    // cvid = trunc(pos * (G-1)) — matches jnp astype(int32) truncation
    const int cx = (int)(px * (float)(Gv - 1));
    const int cy = (int)(py * (float)(Gv - 1));
    const int cz = (int)(pz * (float)(Gv - 1));

    // --- lanes 0..26: one neighbour voxel each, offsets derived in-register ---
    int cnt_eff = 0;
    int vlin    = 0;
    if (lane < 27) {
        const int dx = lane / 9 - 1;
        const int dy = (lane / 3) % 3 - 1;
        const int dz = lane % 3 - 1;
        const int nx = cx + dx, ny = cy + dy, nz = cz + dz;

        const bool inb = (nx >= 0) & (nx <= Gv - 1) &
                         (ny >= 0) & (ny <= Gv - 1) &
                         (nz >= 0) & (nz <= Gv - 1);
        const int xc = min(max(nx, 0), Gv - 1);
        const int yc = min(max(ny, 0), Gv - 1);
        const int zc = min(max(nz, 0), Gv - 1);

        vlin = ((b * Gv + xc) * Gv + yc) * Gv + zc;
        const int cnt = __ldg(&voxel_counts[vlin]);   // mask==(cnt>0): implied
        if (inb) cnt_eff = min(cnt, Pv);
    }

    // --- warp inclusive scan over cnt_eff -> exclusive base per voxel ---
    int incl = cnt_eff;
    #pragma unroll
    for (int d = 1; d < 32; d <<= 1) {
        int y = __shfl_up_sync(FULL, incl, d);
        if (lane >= d) incl += y;
    }
    const int excl  = incl - cnt_eff;
    const int total = __shfl_sync(FULL, incl, 26);    // lanes 27..31 add 0

    // --- single-pass output: slot k = candidate if k < total, else centroid ---
    const size_t row = (size_t)q * Kv;
    if (lane >= total)                       // total may exceed 32; lane<32
        out[row + lane] = (float)c;

    if (lane < 27 && cnt_eff > 0 && excl < Kv) {
        const int* pts = voxel_points + (size_t)vlin * Pv;
        const int lim = min(cnt_eff, Kv - excl);
        #pragma unroll 4
        for (int p = 0; p < lim; ++p) {
            out[row + excl + p] = (float)__ldg(&pts[p]);
        }
    }
}

extern "C" void kernel_launch(void* const* d_in, const int* in_sizes, int n_in,
                              void* d_out, int out_size)
{
    const float* pos           = (const float*)d_in[0];
    const int*   centroids     = (const int*)  d_in[1];
    const int*   voxel_points  = (const int*)  d_in[2];
    const int*   voxel_counts  = (const int*)  d_in[3];
    // d_in[4] = neighbour_voxel_list (derived; unused)
    // d_in[5] = mask                 (derived; unused)
    float*       out           = (float*)      d_out;

    const int totalWarps    = Bv * Sv;   // 16384 queries
    const int threads       = 256;       // 8 warps / CTA
    const int warpsPerBlock = threads / 32;
    const int blocks        = (totalWarps + warpsPerBlock - 1) / warpsPerBlock;

    frnn_kernel<<<blocks, threads>>>(pos, centroids, voxel_points,
                                     voxel_counts, out);
}

// round 9
// speedup vs baseline: 1.0361x; 1.0361x over previous
#include <cuda_runtime.h>
#include <cuda_bf16.h>

// FixedRadiusNearNeighbors: B=4, N=65536, S=4096, G=40, P=16, K=32.
// One warp per (b,s) query. Lanes 0..26 own the 27 neighbour voxels.
//
// R6 changes vs R5:
//  - neighbour_voxel_list (83 MB) never read: content is coords+offset by
//    construction (broadcast meshgrid, data-independent) -> computed in regs.
//  - mask never read: mask == (voxel_counts > 0) by construction.
//  - output written exactly once per slot: slot k gets a candidate iff
//    k < total valid candidates (K == 32 == warpsize), else the centroid.
//    Removes the fill/overwrite double store and the __syncwarp.

#define Gv 40
#define Pv 16
#define Kv 32
#define Bv 4
#define Nv 65536
#define Sv 4096

__global__ __launch_bounds__(256)
void frnn_kernel(const float* __restrict__ pos,
                 const int*   __restrict__ centroids,
                 const int*   __restrict__ voxel_points,
                 const int*   __restrict__ voxel_counts,
                 float*       __restrict__ out)
{
    const unsigned FULL = 0xffffffffu;
    const int lane   = threadIdx.x & 31;
    const int warpId = threadIdx.x >> 5;
    const int q = blockIdx.x * (blockDim.x >> 5) + warpId;
    if (q >= Bv * Sv) return;
    const int b = q >> 12;            // q / Sv

    // --- centroid + its position (lane 0 loads, broadcast) ---
    int   c  = 0;
    float px = 0.f, py = 0.f, pz = 0.f;
    if (lane == 0) {
        c = __ldg(&centroids[q]);
        const float* pp = pos + (((size_t)b << 16) + c) * 3;
        px = __ldg(&pp[0]);
        py = __ldg(&pp[1]);
        pz = __ldg(&pp[2]);
    }
    c  = __shfl_sync(FULL, c, 0);
    px = __shfl_sync(FULL, px, 0);
    py = __shfl_sync(FULL, py, 0);
    pz = __shfl_sync(FULL, pz, 0);

    // cvid = trunc(pos * (G-1)) — matches jnp astype(int32) truncation
    const int cx = (int)(px * (float)(Gv - 1));
    const int cy = (int)(py * (float)(Gv - 1));
    const int cz = (int)(pz * (float)(Gv - 1));

    // --- lanes 0..26: one neighbour voxel each, offsets derived in-register ---
    int cnt_eff = 0;
    int vlin    = 0;
    if (lane < 27) {
        const int dx = lane / 9 - 1;
        const int dy = (lane / 3) % 3 - 1;
        const int dz = lane % 3 - 1;
        const int nx = cx + dx, ny = cy + dy, nz = cz + dz;

        const bool inb = (nx >= 0) & (nx <= Gv - 1) &
                         (ny >= 0) & (ny <= Gv - 1) &
                         (nz >= 0) & (nz <= Gv - 1);
        const int xc = min(max(nx, 0), Gv - 1);
        const int yc = min(max(ny, 0), Gv - 1);
        const int zc = min(max(nz, 0), Gv - 1);

        vlin = ((b * Gv + xc) * Gv + yc) * Gv + zc;
        const int cnt = __ldg(&voxel_counts[vlin]);   // mask==(cnt>0): implied
        if (inb) cnt_eff = min(cnt, Pv);
    }

    // --- warp inclusive scan over cnt_eff -> exclusive base per voxel ---
    int incl = cnt_eff;
    #pragma unroll
    for (int d = 1; d < 32; d <<= 1) {
        int y = __shfl_up_sync(FULL, incl, d);
        if (lane >= d) incl += y;
    }
    const int excl  = incl - cnt_eff;
    const int total = __shfl_sync(FULL, incl, 26);    // lanes 27..31 add 0

    // --- single-pass output: slot k = candidate if k < total, else centroid ---
    const size_t row = (size_t)q * Kv;
    if (lane >= total)                       // total may exceed 32; lane<32
        out[row + lane] = (float)c;

    if (lane < 27 && cnt_eff > 0 && excl < Kv) {
        const int* pts = voxel_points + (size_t)vlin * Pv;
        const int lim = min(cnt_eff, Kv - excl);
        #pragma unroll 4
        for (int p = 0; p < lim; ++p) {
            out[row + excl + p] = (float)__ldg(&pts[p]);
        }
    }
}

extern "C" void kernel_launch(void* const* d_in, const int* in_sizes, int n_in,
                              void* d_out, int out_size)
{
    const float* pos           = (const float*)d_in[0];
    const int*   centroids     = (const int*)  d_in[1];
    const int*   voxel_points  = (const int*)  d_in[2];
    const int*   voxel_counts  = (const int*)  d_in[3];
    // d_in[4] = neighbour_voxel_list (derived; unused)
    // d_in[5] = mask                 (derived; unused)
    float*       out           = (float*)      d_out;

    const int totalWarps    = Bv * Sv;   // 16384 queries
    const int threads       = 256;       // 8 warps / CTA
    const int warpsPerBlock = threads / 32;
    const int blocks        = (totalWarps + warpsPerBlock - 1) / warpsPerBlock;

    frnn_kernel<<<blocks, threads>>>(pos, centroids, voxel_points,
                                     voxel_counts, out);
}

// round 10
// speedup vs baseline: 1.2601x; 1.2161x over previous
#include <cuda_runtime.h>
#include <cuda_bf16.h>

// FixedRadiusNearNeighbors: B=4, N=65536, S=4096, G=40, P=16, K=32.
// One warp per (b,s) query. Lanes 0..26 own the 27 neighbour voxels.
//
// R6 changes vs R5:
//  - neighbour_voxel_list (83 MB) never read: content is coords+offset by
//    construction (broadcast meshgrid, data-independent) -> computed in regs.
//  - mask never read: mask == (voxel_counts > 0) by construction.
//  - output written exactly once per slot: slot k gets a candidate iff
//    k < total valid candidates (K == 32 == warpsize), else the centroid.
//    Removes the fill/overwrite double store and the __syncwarp.

#define Gv 40
#define Pv 16
#define Kv 32
#define Bv 4
#define Nv 65536
#define Sv 4096

__global__ __launch_bounds__(256)
void frnn_kernel(const float* __restrict__ pos,
                 const int*   __restrict__ centroids,
                 const int*   __restrict__ voxel_points,
                 const int*   __restrict__ voxel_counts,
                 float*       __restrict__ out)
{
    const unsigned FULL = 0xffffffffu;
    const int lane   = threadIdx.x & 31;
    const int warpId = threadIdx.x >> 5;
    const int q = blockIdx.x * (blockDim.x >> 5) + warpId;
    if (q >= Bv * Sv) return;
    const int b = q >> 12;            // q / Sv

    // --- centroid + its position (lane 0 loads, broadcast) ---
    int   c  = 0;
    float px = 0.f, py = 0.f, pz = 0.f;
    if (lane == 0) {
        c = __ldg(&centroids[q]);
        const float* pp = pos + (((size_t)b << 16) + c) * 3;
        px = __ldg(&pp[0]);
        py = __ldg(&pp[1]);
        pz = __ldg(&pp[2]);
    }
    c  = __shfl_sync(FULL, c, 0);
    px = __shfl_sync(FULL, px, 0);
    py = __shfl_sync(FULL, py, 0);
    pz = __shfl_sync(FULL, pz, 0);

    // cvid = trunc(pos * (G-1)) — matches jnp astype(int32) truncation
    const int cx = (int)(px * (float)(Gv - 1));
    const int cy = (int)(py * (float)(Gv - 1));
    const int cz = (int)(pz * (float)(Gv - 1));

    // --- lanes 0..26: one neighbour voxel each, offsets derived in-register ---
    int cnt_eff = 0;
    int vlin    = 0;
    if (lane < 27) {
        const int dx = lane / 9 - 1;
        const int dy = (lane / 3) % 3 - 1;
        const int dz = lane % 3 - 1;
        const int nx = cx + dx, ny = cy + dy, nz = cz + dz;

        const bool inb = (nx >= 0) & (nx <= Gv - 1) &
                         (ny >= 0) & (ny <= Gv - 1) &
                         (nz >= 0) & (nz <= Gv - 1);
        const int xc = min(max(nx, 0), Gv - 1);
        const int yc = min(max(ny, 0), Gv - 1);
        const int zc = min(max(nz, 0), Gv - 1);

        vlin = ((b * Gv + xc) * Gv + yc) * Gv + zc;
        const int cnt = __ldg(&voxel_counts[vlin]);   // mask==(cnt>0): implied
        if (inb) cnt_eff = min(cnt, Pv);
    }

    // --- warp inclusive scan over cnt_eff -> exclusive base per voxel ---
    int incl = cnt_eff;
    #pragma unroll
    for (int d = 1; d < 32; d <<= 1) {
        int y = __shfl_up_sync(FULL, incl, d);
        if (lane >= d) incl += y;
    }
    const int excl  = incl - cnt_eff;
    const int total = __shfl_sync(FULL, incl, 26);    // lanes 27..31 add 0

    // --- single-pass output: slot k = candidate if k < total, else centroid ---
    const size_t row = (size_t)q * Kv;
    if (lane >= total)                       // total may exceed 32; lane<32
        out[row + lane] = (float)c;

    if (lane < 27 && cnt_eff > 0 && excl < Kv) {
        const int* pts = voxel_points + (size_t)vlin * Pv;
        const int lim = min(cnt_eff, Kv - excl);
        #pragma unroll 4
        for (int p = 0; p < lim; ++p) {
            out[row + excl + p] = (float)__ldg(&pts[p]);
        }
    }
}

extern "C" void kernel_launch(void* const* d_in, const int* in_sizes, int n_in,
                              void* d_out, int out_size)
{
    const float* pos           = (const float*)d_in[0];
    const int*   centroids     = (const int*)  d_in[1];
    const int*   voxel_points  = (const int*)  d_in[2];
    const int*   voxel_counts  = (const int*)  d_in[3];
    // d_in[4] = neighbour_voxel_list (derived; unused)
    // d_in[5] = mask                 (derived; unused)
    float*       out           = (float*)      d_out;

    const int totalWarps    = Bv * Sv;   // 16384 queries
    const int threads       = 256;       // 8 warps / CTA
    const int warpsPerBlock = threads / 32;
    const int blocks        = (totalWarps + warpsPerBlock - 1) / warpsPerBlock;

    frnn_kernel<<<blocks, threads>>>(pos, centroids, voxel_points,
                                     voxel_counts, out);
}